// round 2
// baseline (speedup 1.0000x reference)
#include <cuda_runtime.h>
#include <cstdint>
#include <math.h>

// ============================================================================
// Constants
// ============================================================================
#define NSTEP  60
#define NB     65536
#define G      256           // table nodes per step
#define HID    128
#define FEE_C  0.0196f
#define LAM_C  0.01f
#define DT_C   (1.0f/12.0f)
#define TEXP_C 5.0f

// ============================================================================
// Device scratch (static — no allocations allowed)
// ============================================================================
__device__ int   d_lo_bits[NSTEP];
__device__ int   d_hi_bits[NSTEP];
__device__ float d_table[NSTEP * G];

// ============================================================================
// k_init: reset min/max scratch (must run every graph replay)
// ============================================================================
__global__ void k_init()
{
    int s = threadIdx.x;
    if (s < NSTEP) {
        d_lo_bits[s] = 0x7f7fffff;   // FLT_MAX bits
        d_hi_bits[s] = 0;            // < any positive float
    }
}

// ============================================================================
// k_minmax: per-step realized min/max of spots (rows 0..59).
// spots > 0 always, so float ordering == int-bits ordering.
// grid (60, 4): blockIdx.x = step, blockIdx.y = quarter of the 65536 row.
// ============================================================================
__global__ void __launch_bounds__(256) k_minmax(const float* __restrict__ spots)
{
    const int s = blockIdx.x;
    const float4* row = (const float4*)(spots + (size_t)s * NB + blockIdx.y * (NB / 4));
    float lo = 3.4e38f, hi = 0.0f;
    for (int i = threadIdx.x; i < NB / 16; i += 256) {   // 4096 float4 per quarter
        float4 v = row[i];
        lo = fminf(lo, fminf(fminf(v.x, v.y), fminf(v.z, v.w)));
        hi = fmaxf(hi, fmaxf(fmaxf(v.x, v.y), fmaxf(v.z, v.w)));
    }
    #pragma unroll
    for (int o = 16; o; o >>= 1) {
        lo = fminf(lo, __shfl_xor_sync(0xffffffffu, lo, o));
        hi = fmaxf(hi, __shfl_xor_sync(0xffffffffu, hi, o));
    }
    __shared__ float slo[8], shi[8];
    if ((threadIdx.x & 31) == 0) { slo[threadIdx.x >> 5] = lo; shi[threadIdx.x >> 5] = hi; }
    __syncthreads();
    if (threadIdx.x == 0) {
        for (int w = 1; w < 8; w++) { lo = fminf(lo, slo[w]); hi = fmaxf(hi, shi[w]); }
        atomicMin(&d_lo_bits[s], __float_as_int(lo));
        atomicMax(&d_hi_bits[s], __float_as_int(hi));
    }
}

// ============================================================================
// k_table: exact MLP evaluation at 60 x 256 grid nodes -> delta table.
//   node (s, i): x = lo_s + i*(hi_s-lo_s)/(G-1)
//   net = W3 . relu(W2^T relu(x*W1[0] + t*W1[1] + b1) + b2) + b3
//   table = -(net^2) * (1 - exp(-LAM*(TEXP-t))) * 100
// 4 threads per node (consecutive lanes), each owns 32 of the 128 k-dims.
// 61440 threads total, 240 CTAs x 256.
// ============================================================================
__global__ void __launch_bounds__(256) k_table(
    const float* __restrict__ W1, const float* __restrict__ b1,
    const float* __restrict__ W2, const float* __restrict__ b2,
    const float* __restrict__ W3, const float* __restrict__ b3)
{
    __shared__ float sW1a[HID], sW1b[HID], sb1[HID], sb2[HID], sw3[HID];
    __shared__ float sb3;
    extern __shared__ float sW2t[];               // [128][132] padded transpose

    const int tid = threadIdx.x;
    for (int i = tid; i < HID; i += 256) {
        sW1a[i] = W1[i]; sW1b[i] = W1[HID + i];
        sb1[i] = b1[i];  sb2[i] = b2[i]; sw3[i] = W3[i];
    }
    if (tid == 0) sb3 = b3[0];
    for (int idx = tid; idx < HID * HID; idx += 256) {
        int k = idx >> 7, j = idx & 127;
        sW2t[j * 132 + k] = W2[idx];              // W2t[j][k] = W2[k][j]
    }
    __syncthreads();

    const int gid  = blockIdx.x * 256 + tid;      // 0..61439
    const int node = gid >> 2;                    // 0..15359
    const int q    = gid & 3;                     // k-quarter
    const int s    = node >> 8;
    const int i    = node & (G - 1);
    const float t  = (float)s * DT_C;
    const float lo = __int_as_float(d_lo_bits[s]);
    const float hi = __int_as_float(d_hi_bits[s]);
    const float x  = lo + (hi - lo) * ((float)i * (1.0f / (G - 1)));

    // layer 1 for this thread's 32 k's
    float h1[32];
    const int k0 = q * 32;
    #pragma unroll
    for (int kk = 0; kk < 32; kk++) {
        int k = k0 + kk;
        float c = fmaf(t, sW1b[k], sb1[k]);
        h1[kk] = fmaxf(fmaf(x, sW1a[k], c), 0.0f);
    }

    // layer 2 + 3: per j, 32 partial FMAs then quartet shfl-reduce
    float outacc = 0.0f;
    #pragma unroll 2
    for (int j = 0; j < HID; j++) {
        const float4* r = (const float4*)(sW2t + j * 132 + k0);
        float a0 = 0.f, a1 = 0.f, a2 = 0.f, a3 = 0.f;
        #pragma unroll
        for (int v = 0; v < 8; v++) {
            float4 w = r[v];
            a0 = fmaf(h1[4 * v + 0], w.x, a0);
            a1 = fmaf(h1[4 * v + 1], w.y, a1);
            a2 = fmaf(h1[4 * v + 2], w.z, a2);
            a3 = fmaf(h1[4 * v + 3], w.w, a3);
        }
        float sum = (a0 + a1) + (a2 + a3);
        sum += __shfl_xor_sync(0xffffffffu, sum, 1);
        sum += __shfl_xor_sync(0xffffffffu, sum, 2);
        float h2 = fmaxf(sum + sb2[j], 0.0f);
        outacc = fmaf(h2, sw3[j], outacc);
    }

    if (q == 0) {
        float net = outacc + sb3;
        float fdelta = (1.0f - expf(-LAM_C * (TEXP_C - t))) * 100.0f;
        d_table[node] = -(net * net) * fdelta;
    }
}

// ============================================================================
// k_pnl: per-path PnL.
//   account = 100*spot*e_fee ; fee = FEE*DT*account*e_lam = C1*spot
//   payout  = LAM*DT*max(100-account,0)*e_lam = C2*max(100 - C3*spot, 0)
//   pnl += fee - payout + table_s(spot) * (spot_next - spot)
// Table in SMEM (61.4 KB) -> 2 CTAs/SM possible.
// ============================================================================
__global__ void __launch_bounds__(256) k_pnl(const float* __restrict__ spots,
                                             float* __restrict__ out)
{
    extern __shared__ float stab[];               // [NSTEP*G] delta values
    __shared__ float4 scst[NSTEP];                // (lo, scale, C1, C2)
    __shared__ float  sc3[NSTEP];                 // C3 = 100*e_fee

    const int tid = threadIdx.x;
    for (int idx = tid; idx < NSTEP * G; idx += 256)
        stab[idx] = d_table[idx];
    if (tid < NSTEP) {
        float t = (float)tid * DT_C;
        float e_fee = expf(-FEE_C * t), e_lam = expf(-LAM_C * t);
        float lo = __int_as_float(d_lo_bits[tid]);
        float hi = __int_as_float(d_hi_bits[tid]);
        float scale = (hi - lo > 1e-30f) ? (float)(G - 1) / (hi - lo) : 0.0f;
        scst[tid] = make_float4(lo, scale,
                                FEE_C * DT_C * 100.0f * e_fee * e_lam,
                                LAM_C * DT_C * e_lam);
        sc3[tid] = 100.0f * e_fee;
    }
    __syncthreads();

    const int path = blockIdx.x * 256 + tid;
    float spot = spots[path];
    float pnl = 0.0f;

    #pragma unroll 4
    for (int s = 0; s < NSTEP; s++) {
        float spotn = spots[(size_t)(s + 1) * NB + path];
        float4 C = scst[s];
        float u = (spot - C.x) * C.y;
        int   ii = (int)u;
        ii = max(0, min(ii, G - 2));
        float fr = u - (float)ii;
        float g0 = stab[s * G + ii];
        float g1 = stab[s * G + ii + 1];
        float d  = fmaf(fr, g1 - g0, g0);
        float acct = sc3[s] * spot;
        float fee  = C.z * spot;
        float pay  = C.w * fmaxf(100.0f - acct, 0.0f);
        pnl += fee - pay + d * (spotn - spot);
        spot = spotn;
    }
    out[path] = pnl;
}

// ============================================================================
// Launch (graph-capturable: 4 kernel launches, no allocs, no sync)
// ============================================================================
extern "C" void kernel_launch(void* const* d_in, const int* in_sizes, int n_in,
                              void* d_out, int out_size)
{
    const float* spots = (const float*)d_in[0];
    const float* W1    = (const float*)d_in[1];
    const float* b1    = (const float*)d_in[2];
    const float* W2    = (const float*)d_in[3];
    const float* b2    = (const float*)d_in[4];
    const float* W3    = (const float*)d_in[5];
    const float* b3    = (const float*)d_in[6];
    float* out = (float*)d_out;

    static bool attr_done = false;
    if (!attr_done) {
        cudaFuncSetAttribute(k_table, cudaFuncAttributeMaxDynamicSharedMemorySize,
                             128 * 132 * 4);
        cudaFuncSetAttribute(k_pnl, cudaFuncAttributeMaxDynamicSharedMemorySize,
                             NSTEP * G * 4);
        attr_done = true;
    }

    k_init<<<1, 64>>>();
    k_minmax<<<dim3(NSTEP, 4), 256>>>(spots);
    k_table<<<(NSTEP * G * 4) / 256, 256, 128 * 132 * 4>>>(W1, b1, W2, b2, W3, b3);
    k_pnl<<<NB / 256, 256, NSTEP * G * 4>>>(spots, out);
}

// round 6
// speedup vs baseline: 4.9508x; 4.9508x over previous
#include <cuda_runtime.h>
#include <cstdint>
#include <math.h>

// ============================================================================
// Constants
// ============================================================================
#define NSTEP  60
#define NB     65536
#define G      128           // table nodes per step
#define HID    128
#define FEE_C  0.0196f
#define LAM_C  0.01f
#define DT_C   (1.0f/12.0f)
#define TEXP_C 5.0f

// ============================================================================
// Device scratch (static — no allocations allowed)
// ============================================================================
__device__ float2 d_part[NSTEP * 2];     // per (step, half) (lo, hi) partials
__device__ float  d_table[NSTEP * G];    // delta(s, x_i)

// ============================================================================
// k_minmax: per-step realized min/max of spots rows 0..59.
// 120 blocks: blockIdx.x = 2*s + half. Each block scans half a row and
// writes its (lo,hi) to a UNIQUE slot -> no atomics, no init kernel,
// graph-replay safe by construction.
// ============================================================================
__global__ void __launch_bounds__(256) k_minmax(const float* __restrict__ spots)
{
    const int s    = blockIdx.x >> 1;
    const int half = blockIdx.x & 1;
    const float4* p = (const float4*)(spots + (size_t)s * NB + half * (NB / 2));

    float lo = 3.4e38f, hi = 0.0f;
    #pragma unroll 4
    for (int i = threadIdx.x; i < NB / 8; i += 256) {     // 8192 float4
        float4 v = p[i];
        lo = fminf(lo, fminf(fminf(v.x, v.y), fminf(v.z, v.w)));
        hi = fmaxf(hi, fmaxf(fmaxf(v.x, v.y), fmaxf(v.z, v.w)));
    }
    #pragma unroll
    for (int o = 16; o; o >>= 1) {
        lo = fminf(lo, __shfl_xor_sync(0xffffffffu, lo, o));
        hi = fmaxf(hi, __shfl_xor_sync(0xffffffffu, hi, o));
    }
    __shared__ float slo[8], shi[8];
    if ((threadIdx.x & 31) == 0) { slo[threadIdx.x >> 5] = lo; shi[threadIdx.x >> 5] = hi; }
    __syncthreads();
    if (threadIdx.x == 0) {
        #pragma unroll
        for (int w = 1; w < 8; w++) { lo = fminf(lo, slo[w]); hi = fmaxf(hi, shi[w]); }
        d_part[blockIdx.x] = make_float2(lo, hi);
    }
}

// ============================================================================
// k_table: exact MLP evaluation at 60 x 128 grid nodes.
// 240 blocks x 512 threads. Each warp handles TWO nodes (same step s,
// i and i+64): h1 vectors in SMEM (16B-aligned!); each lane owns
// j = lane + 32*jj (jj=0..3) output neurons for both nodes, so every W2^T
// smem read feeds 8 FMAs. One shfl-reduce pass at the end (not per-j).
// ============================================================================
__global__ void __launch_bounds__(512) k_table(
    const float* __restrict__ W1, const float* __restrict__ b1,
    const float* __restrict__ W2, const float* __restrict__ b2,
    const float* __restrict__ W3, const float* __restrict__ b3)
{
    __shared__ float sW1a[HID], sW1b[HID], sb1[HID], sb2[HID], sw3[HID];
    __shared__ float sb3;
    __shared__ __align__(16) float sh1[16 * 2 * HID];  // per warp: 2 nodes x 128
    extern __shared__ float sW2t[];               // [128][132] transpose, padded

    const int tid  = threadIdx.x;
    const int w    = tid >> 5;
    const int lane = tid & 31;

    for (int i = tid; i < HID; i += 512) {
        sW1a[i] = W1[i]; sW1b[i] = W1[HID + i];
        sb1[i] = b1[i];  sb2[i] = b2[i]; sw3[i] = W3[i];
    }
    if (tid == 0) sb3 = b3[0];
    for (int idx = tid; idx < HID * HID; idx += 512) {
        int k = idx >> 7, j = idx & 127;
        sW2t[j * 132 + k] = W2[idx];              // W2t[j][k] = W2[k][j]
    }
    __syncthreads();

    const int W_ = blockIdx.x * 16 + w;           // global warp 0..3839
    const int s  = W_ >> 6;                       // step
    const int pr = W_ & 63;                       // node pair
    const int i0 = pr, i1 = pr + 64;
    const float t = (float)s * DT_C;

    float2 pa = d_part[2 * s], pb = d_part[2 * s + 1];
    const float lo = fminf(pa.x, pb.x);
    const float hi = fmaxf(pa.y, pb.y);
    const float x0 = lo + (hi - lo) * ((float)i0 * (1.0f / (G - 1)));
    const float x1 = lo + (hi - lo) * ((float)i1 * (1.0f / (G - 1)));

    // layer 1: lane computes k = 4*lane .. 4*lane+3 for both nodes
    float* h1a = sh1 + w * 2 * HID;
    float* h1b = h1a + HID;
    {
        float4 va, vb;
        const int k = 4 * lane;
        float c0 = fmaf(t, sW1b[k + 0], sb1[k + 0]);
        float c1 = fmaf(t, sW1b[k + 1], sb1[k + 1]);
        float c2 = fmaf(t, sW1b[k + 2], sb1[k + 2]);
        float c3 = fmaf(t, sW1b[k + 3], sb1[k + 3]);
        va.x = fmaxf(fmaf(x0, sW1a[k + 0], c0), 0.0f);
        va.y = fmaxf(fmaf(x0, sW1a[k + 1], c1), 0.0f);
        va.z = fmaxf(fmaf(x0, sW1a[k + 2], c2), 0.0f);
        va.w = fmaxf(fmaf(x0, sW1a[k + 3], c3), 0.0f);
        vb.x = fmaxf(fmaf(x1, sW1a[k + 0], c0), 0.0f);
        vb.y = fmaxf(fmaf(x1, sW1a[k + 1], c1), 0.0f);
        vb.z = fmaxf(fmaf(x1, sW1a[k + 2], c2), 0.0f);
        vb.w = fmaxf(fmaf(x1, sW1a[k + 3], c3), 0.0f);
        *(float4*)(h1a + k) = va;
        *(float4*)(h1b + k) = vb;
    }
    __syncwarp();

    // layer 2: lane accumulates j = lane + 32*jj for both nodes
    float aca[4] = {0, 0, 0, 0};
    float acb[4] = {0, 0, 0, 0};
    #pragma unroll 4
    for (int kc = 0; kc < 32; kc++) {
        float4 ha = *(const float4*)(h1a + 4 * kc);   // broadcast
        float4 hb = *(const float4*)(h1b + 4 * kc);   // broadcast
        #pragma unroll
        for (int jj = 0; jj < 4; jj++) {
            const float4 wv = *(const float4*)(sW2t + (lane + 32 * jj) * 132 + 4 * kc);
            aca[jj] = fmaf(wv.x, ha.x, aca[jj]); acb[jj] = fmaf(wv.x, hb.x, acb[jj]);
            aca[jj] = fmaf(wv.y, ha.y, aca[jj]); acb[jj] = fmaf(wv.y, hb.y, acb[jj]);
            aca[jj] = fmaf(wv.z, ha.z, aca[jj]); acb[jj] = fmaf(wv.z, hb.z, acb[jj]);
            aca[jj] = fmaf(wv.w, ha.w, aca[jj]); acb[jj] = fmaf(wv.w, hb.w, acb[jj]);
        }
    }

    // layer 3 partials
    float o0 = 0.0f, o1 = 0.0f;
    #pragma unroll
    for (int jj = 0; jj < 4; jj++) {
        const int j = lane + 32 * jj;
        o0 = fmaf(fmaxf(aca[jj] + sb2[j], 0.0f), sw3[j], o0);
        o1 = fmaf(fmaxf(acb[jj] + sb2[j], 0.0f), sw3[j], o1);
    }
    #pragma unroll
    for (int o = 16; o; o >>= 1) {
        o0 += __shfl_xor_sync(0xffffffffu, o0, o);
        o1 += __shfl_xor_sync(0xffffffffu, o1, o);
    }
    if (lane == 0) {
        const float fdelta = (1.0f - expf(-LAM_C * (TEXP_C - t))) * 100.0f;
        float n0 = o0 + sb3, n1 = o1 + sb3;
        d_table[s * G + i0] = -(n0 * n0) * fdelta;
        d_table[s * G + i1] = -(n1 * n1) * fdelta;
    }
}

// ============================================================================
// k_pnl: per-path PnL with (value, slope) table pairs in SMEM and a 2-deep
// software pipeline on the spot stream.
//   pnl += C1*spot - C2*max(100 - C3*spot, 0) + table_s(spot)*(spotn - spot)
// ============================================================================
__global__ void __launch_bounds__(256) k_pnl(const float* __restrict__ spots,
                                             float* __restrict__ out)
{
    extern __shared__ float2 stab[];              // [NSTEP*G] (value, slope)
    __shared__ float4 scst[NSTEP];                // (lo, scale, C1, C2)
    __shared__ float  sc3[NSTEP];                 // C3 = 100*e_fee

    const int tid = threadIdx.x;
    for (int idx = tid; idx < NSTEP * G; idx += 256) {
        int i = idx & (G - 1);
        float a = d_table[idx];
        float b = d_table[idx + (i < G - 1 ? 1 : 0)];
        stab[idx] = make_float2(a, b - a);
    }
    if (tid < NSTEP) {
        float t = (float)tid * DT_C;
        float e_fee = expf(-FEE_C * t), e_lam = expf(-LAM_C * t);
        float2 pa = d_part[2 * tid], pb = d_part[2 * tid + 1];
        float lo = fminf(pa.x, pb.x);
        float hi = fmaxf(pa.y, pb.y);
        float scale = (hi - lo > 1e-30f) ? (float)(G - 1) / (hi - lo) : 0.0f;
        scst[tid] = make_float4(lo, scale,
                                FEE_C * DT_C * 100.0f * e_fee * e_lam,
                                LAM_C * DT_C * e_lam);
        sc3[tid] = 100.0f * e_fee;
    }
    __syncthreads();

    const int path = blockIdx.x * 256 + tid;
    float sp0 = spots[path];
    float sp1 = spots[(size_t)NB + path];
    float pnl = 0.0f;

    #pragma unroll 4
    for (int s = 0; s < NSTEP; s++) {
        const int r2 = (s + 2 <= NSTEP) ? (s + 2) : NSTEP;
        float sp2 = spots[(size_t)r2 * NB + path];   // prefetch 2 ahead

        float4 C = scst[s];
        float u = (sp0 - C.x) * C.y;
        int   ii = (int)u;
        ii = max(0, min(ii, G - 2));
        float fr = u - (float)ii;
        float2 g = stab[s * G + ii];
        float d  = fmaf(fr, g.y, g.x);
        float fee = C.z * sp0;
        float pay = C.w * fmaxf(100.0f - sc3[s] * sp0, 0.0f);
        pnl += fee - pay + d * (sp1 - sp0);

        sp0 = sp1;
        sp1 = sp2;
    }
    out[path] = pnl;
}

// ============================================================================
// Launch (graph-capturable: 3 kernel launches, no allocs, no sync).
// ============================================================================
extern "C" void kernel_launch(void* const* d_in, const int* in_sizes, int n_in,
                              void* d_out, int out_size)
{
    const float* spots = (const float*)d_in[0];
    const float* W1    = (const float*)d_in[1];
    const float* b1    = (const float*)d_in[2];
    const float* W2    = (const float*)d_in[3];
    const float* b2    = (const float*)d_in[4];
    const float* W3    = (const float*)d_in[5];
    const float* b3    = (const float*)d_in[6];
    float* out = (float*)d_out;

    static bool attr_done = false;
    if (!attr_done) {
        cudaFuncSetAttribute(k_table, cudaFuncAttributeMaxDynamicSharedMemorySize,
                             HID * 132 * 4);
        cudaFuncSetAttribute(k_pnl, cudaFuncAttributeMaxDynamicSharedMemorySize,
                             NSTEP * G * 8);
        attr_done = true;
    }

    k_minmax<<<NSTEP * 2, 256>>>(spots);
    k_table<<<240, 512, HID * 132 * 4>>>(W1, b1, W2, b2, W3, b3);
    k_pnl<<<NB / 256, 256, NSTEP * G * 8>>>(spots, out);
}